// round 13
// baseline (speedup 1.0000x reference)
#include <cuda_runtime.h>
#include <cuda_fp16.h>
#include <math.h>

// ---------------------------------------------------------------------------
//   x:[B,256]  W1:[512,273] b1:[512]  W2:[512,512] b2  W3:[512,512] b3
//   Wih:[2048,512] Whh:[2048,512] bih:[2048] bhh:[2048]  sentence_len (int)
//   out:[B,T,512] fp32
//
// compute_103 virtual arch -> no tcgen05. fp16 mma.sync m16n8k16 (fp32 acc),
// pair-permuted fp16 operands (pure cp.async + LDS.128 + HMMA mainloop).
// R6-proven BK=32 tile/layout/swizzle; THIS ROUND: 6-stage cp.async pipeline
// (96KB dynamic smem) with uniform wait_group 4 -> 5 loads in flight.
// LSTM algebra: inp==h after step 0 -> Wcomb = Wih+Whh halves LSTM FLOPs.
// LSTM cell fused into gates-GEMM epilogue (gate-interleaved N + lane^1).
// ---------------------------------------------------------------------------

#define MAXB 8192
#define NSTAGE 6
#define SMEM_BYTES (NSTAGE * 1024 * 16)   // 6 stages x (8KB A + 8KB B) = 96KB

__device__ __align__(256) __half g_W1x[512 * 256];      // perm half W1[:,17:273]
__device__ __align__(256) float  g_b1eff[512];          // b1 + W1[:, 20-len]
__device__ __align__(256) __half g_WcombI[2048 * 512];  // gate-interleaved perm (Wih+Whh)
__device__ __align__(256) __half g_WihI[2048 * 512];    // gate-interleaved perm Wih (t=0)
__device__ __align__(256) float  g_biascI[2048];        // gate-interleaved bih+bhh
__device__ __align__(256) __half g_W2p[512 * 512];
__device__ __align__(256) __half g_W3p[512 * 512];
__device__ __align__(256) __half g_xp[MAXB * 256];      // perm half x
__device__ __align__(256) __half g_h1[MAXB * 512];
__device__ __align__(256) __half g_h2[MAXB * 512];
__device__ __align__(256) __half g_hA[MAXB * 512];      // perm half h ping
__device__ __align__(256) __half g_hB[MAXB * 512];      // perm half h pong
__device__ __align__(256) float  g_c[MAXB * 512];

// ---------------------------------------------------------------------------
// helpers
// ---------------------------------------------------------------------------
// involutive permutation on 4-bit index: swap the two 2-bit fields.
// Applied to PAIR indices within 16-pair (32-half) blocks.
__device__ __host__ __forceinline__ int perm16(int p) {
    return (p & ~15) | ((p & 3) << 2) | ((p >> 2) & 3);
}
// stored half position -> original k
__device__ __forceinline__ int kmap(int pos) {
    return (pos & ~31) | (perm16((pos >> 1) & 15) << 1) | (pos & 1);
}

__device__ __forceinline__ float fsig(float x)  { return 1.f / (1.f + __expf(-x)); }
__device__ __forceinline__ float ftanh(float x) { return 2.f / (1.f + __expf(-2.f * x)) - 1.f; }
__device__ __forceinline__ float sigacc(float x) { return 1.f / (1.f + expf(-x)); }

__device__ __forceinline__ void cpasync16(void* dst, const void* src) {
    unsigned d = (unsigned)__cvta_generic_to_shared(dst);
    asm volatile("cp.async.cg.shared.global [%0], [%1], 16;\n" :: "r"(d), "l"(src));
}

__device__ __forceinline__ void mma16(float* c,
                                      unsigned a0, unsigned a1, unsigned a2, unsigned a3,
                                      unsigned b0, unsigned b1) {
    asm volatile(
        "mma.sync.aligned.m16n8k16.row.col.f32.f16.f16.f32 "
        "{%0,%1,%2,%3}, {%4,%5,%6,%7}, {%8,%9}, {%0,%1,%2,%3};\n"
        : "+f"(c[0]), "+f"(c[1]), "+f"(c[2]), "+f"(c[3])
        : "r"(a0), "r"(a1), "r"(a2), "r"(a3), "r"(b0), "r"(b1));
}

// ---------------------------------------------------------------------------
// prep: permuted fp16 operand copies, fused biases.
// ---------------------------------------------------------------------------
__global__ void prep_kernel(const float* __restrict__ x,
                            const float* __restrict__ W1, const float* __restrict__ b1,
                            const float* __restrict__ W2, const float* __restrict__ W3,
                            const float* __restrict__ Wih, const float* __restrict__ Whh,
                            const float* __restrict__ bih, const float* __restrict__ bhh,
                            const int* __restrict__ slen, int B)
{
    int i = blockIdx.x * blockDim.x + threadIdx.x;

    if (i < 2048 * 512) {                       // LSTM weights: interleave N, permute K
        int np = i >> 9, p = i & 511;
        int gate = np & 3, j = np >> 2;
        int orig = (gate * 512 + j) * 512 + kmap(p);
        float wv = Wih[orig];
        float wh = Whh[orig];
        g_WihI[i]   = __float2half_rn(wv);
        g_WcombI[i] = __float2half_rn(wv + wh);
    }
    if (i < 512 * 512) {                        // W2, W3 (K-permuted)
        int n = i >> 9, p = i & 511;
        int k = kmap(p);
        g_W2p[i] = __float2half_rn(W2[n * 512 + k]);
        g_W3p[i] = __float2half_rn(W3[n * 512 + k]);
    }
    if (i < 512 * 256) {                        // W1 noise columns
        int n = i >> 8, p = i & 255;
        g_W1x[i] = __float2half_rn(W1[n * 273 + 17 + kmap(p)]);
    }
    if (i < B * 256) {                          // x permuted fp16
        int b = i >> 8, p = i & 255;
        g_xp[i] = __float2half_rn(x[b * 256 + kmap(p)]);
    }
    if (i < 2048) {                             // interleaved fused bias
        int gate = i & 3, j = i >> 2;
        g_biascI[i] = bih[gate * 512 + j] + bhh[gate * 512 + j];
    }
    if (i < 512) {
        int hot = 20 - *slen;
        g_b1eff[i] = b1[i] + W1[i * 273 + hot];
    }
}

// ---------------------------------------------------------------------------
// MLP GEMM: C[M,N] = act( A[M,K] * W[N,K]^T + bias[N] ), half operands,
// pair-permuted K. Block 128x128, BK=32 halves, 6-stage cp.async pipeline
// (dynamic smem), 8 warps (2x4), warp 64x32, mma m16n8k16.
// Stage s: A at S4[s*1024], B at S4[s*1024+512]; row layout 4 uint4 with
// swizzle lc ^ ((row>>1)&3)  (R6-proven conflict-free).
// ACT: 1=relu, 2=sigmoid. Stores permuted half (feeds next GEMM as A).
// ---------------------------------------------------------------------------
template <int ACT>
__global__ __launch_bounds__(256, 2)
void gemm_mlp(const __half* __restrict__ A, int lda,
              const __half* __restrict__ Bm, int ldb,
              const float* __restrict__ bias,
              __half* __restrict__ C, int ldc, int K)
{
    extern __shared__ __align__(1024) char dsm[];
    uint4* S4 = (uint4*)dsm;

    const int tid  = threadIdx.x;
    const int lane = tid & 31;
    const int warp = tid >> 5;
    const int wm = (warp >> 2) * 64;
    const int wn = (warp & 3) * 32;
    const int r = lane >> 2;
    const int q = lane & 3;

    const __half* Ab = A  + (size_t)blockIdx.y * 128 * lda;
    const __half* Bb = Bm + (size_t)blockIdx.x * 128 * ldb;

    const int lr = tid >> 2;          // 0..63 (and +64)
    const int lc = tid & 3;           // chunk 0..3
    const int KT = K >> 5;            // 32 halves per tile

    float acc[4][4][4];
    #pragma unroll
    for (int i = 0; i < 4; i++)
        #pragma unroll
        for (int j = 0; j < 4; j++)
            #pragma unroll
            for (int k = 0; k < 4; k++) acc[i][j][k] = 0.f;

    auto ld_stage = [&](int s, int kt, bool valid) {
        if (valid) {
            const int k0 = kt << 5;
            int row = lr;
            cpasync16(&S4[s * 1024 + row * 4 + (lc ^ ((row >> 1) & 3))],
                      Ab + (size_t)row * lda + k0 + 8 * lc);
            cpasync16(&S4[s * 1024 + 512 + row * 4 + (lc ^ ((row >> 1) & 3))],
                      Bb + (size_t)row * ldb + k0 + 8 * lc);
            row = lr + 64;
            cpasync16(&S4[s * 1024 + row * 4 + (lc ^ ((row >> 1) & 3))],
                      Ab + (size_t)row * lda + k0 + 8 * lc);
            cpasync16(&S4[s * 1024 + 512 + row * 4 + (lc ^ ((row >> 1) & 3))],
                      Bb + (size_t)row * ldb + k0 + 8 * lc);
        }
        asm volatile("cp.async.commit_group;\n" ::);   // one group per tile slot
    };

    #pragma unroll
    for (int p = 0; p < NSTAGE - 1; p++) ld_stage(p, p, p < KT);

    int s = 0, sld = NSTAGE - 1;
    for (int kt = 0; kt < KT; kt++) {
        asm volatile("cp.async.wait_group %0;\n" :: "n"(NSTAGE - 2));
        __syncthreads();

        ld_stage(sld, kt + NSTAGE - 1, kt + NSTAGE - 1 < KT);

        uint4 af[4][2], bf[4];
        #pragma unroll
        for (int mi = 0; mi < 4; mi++) {
            int r0 = wm + mi * 16 + r;
            af[mi][0] = S4[s * 1024 + r0 * 4 + (q ^ ((r0 >> 1) & 3))];
            int r1 = r0 + 8;
            af[mi][1] = S4[s * 1024 + r1 * 4 + (q ^ ((r1 >> 1) & 3))];
        }
        #pragma unroll
        for (int ni = 0; ni < 4; ni++) {
            int rb = wn + ni * 8 + r;
            bf[ni] = S4[s * 1024 + 512 + rb * 4 + (q ^ ((rb >> 1) & 3))];
        }

        #pragma unroll
        for (int mi = 0; mi < 4; mi++)
            #pragma unroll
            for (int ni = 0; ni < 4; ni++)
                mma16(acc[mi][ni], af[mi][0].x, af[mi][1].x, af[mi][0].y, af[mi][1].y,
                      bf[ni].x, bf[ni].y);
        #pragma unroll
        for (int mi = 0; mi < 4; mi++)
            #pragma unroll
            for (int ni = 0; ni < 4; ni++)
                mma16(acc[mi][ni], af[mi][0].z, af[mi][1].z, af[mi][0].w, af[mi][1].w,
                      bf[ni].z, bf[ni].w);

        s = (s + 1 == NSTAGE) ? 0 : s + 1;
        sld = (sld + 1 == NSTAGE) ? 0 : sld + 1;
    }

    #pragma unroll
    for (int mi = 0; mi < 4; mi++) {
        int m0 = blockIdx.y * 128 + wm + mi * 16 + r;
        #pragma unroll
        for (int ni = 0; ni < 4; ni++) {
            int n = blockIdx.x * 128 + wn + ni * 8 + 2 * q;
            float b0v = bias[n], b1v = bias[n + 1];
            float v00 = acc[mi][ni][0] + b0v, v01 = acc[mi][ni][1] + b1v;
            float v10 = acc[mi][ni][2] + b0v, v11 = acc[mi][ni][3] + b1v;
            if (ACT == 1) {
                v00 = fmaxf(v00, 0.f); v01 = fmaxf(v01, 0.f);
                v10 = fmaxf(v10, 0.f); v11 = fmaxf(v11, 0.f);
            } else {
                v00 = sigacc(v00); v01 = sigacc(v01);
                v10 = sigacc(v10); v11 = sigacc(v11);
            }
            // (n, n+1) is one K-pair: store half2 at the permuted pair slot
            int sp = (n & ~31) | (perm16((n >> 1) & 15) << 1);
            *(__half2*)(C + (size_t)m0 * ldc + sp)       = __floats2half2_rn(v00, v01);
            *(__half2*)(C + (size_t)(m0 + 8) * ldc + sp) = __floats2half2_rn(v10, v11);
        }
    }
}

// ---------------------------------------------------------------------------
// Fused gates-GEMM + LSTM cell (same 6-stage BK=32 mainloop, KT=16).
// ---------------------------------------------------------------------------
template <int FIRST>
__global__ __launch_bounds__(256, 2)
void gemm_lstm(const __half* __restrict__ A,     // hin [B,512] perm half
               const __half* __restrict__ Bm,    // WgI [2048,512]
               const float* __restrict__ bias,   // biascI [2048]
               float* __restrict__ cmem,         // g_c [B,512]
               float* __restrict__ outp,         // out [B,T,512]
               __half* __restrict__ hout,        // next h [B,512] perm half
               int t, int T)
{
    extern __shared__ __align__(1024) char dsm[];
    uint4* S4 = (uint4*)dsm;

    const int tid  = threadIdx.x;
    const int lane = tid & 31;
    const int warp = tid >> 5;
    const int wm = (warp >> 2) * 64;
    const int wn = (warp & 3) * 32;
    const int r = lane >> 2;
    const int q = lane & 3;

    const __half* Ab = A  + (size_t)blockIdx.y * 128 * 512;
    const __half* Bb = Bm + (size_t)blockIdx.x * 128 * 512;

    const int lr = tid >> 2;
    const int lc = tid & 3;
    const int KT = 16;                // K = 512 halves / 32

    float acc[4][4][4];
    #pragma unroll
    for (int i = 0; i < 4; i++)
        #pragma unroll
        for (int j = 0; j < 4; j++)
            #pragma unroll
            for (int k = 0; k < 4; k++) acc[i][j][k] = 0.f;

    auto ld_stage = [&](int s, int kt, bool valid) {
        if (valid) {
            const int k0 = kt << 5;
            int row = lr;
            cpasync16(&S4[s * 1024 + row * 4 + (lc ^ ((row >> 1) & 3))],
                      Ab + (size_t)row * 512 + k0 + 8 * lc);
            cpasync16(&S4[s * 1024 + 512 + row * 4 + (lc ^ ((row >> 1) & 3))],
                      Bb + (size_t)row * 512 + k0 + 8 * lc);
            row = lr + 64;
            cpasync16(&S4[s * 1024 + row * 4 + (lc ^ ((row >> 1) & 3))],
                      Ab + (size_t)row * 512 + k0 + 8 * lc);
            cpasync16(&S4[s * 1024 + 512 + row * 4 + (lc ^ ((row >> 1) & 3))],
                      Bb + (size_t)row * 512 + k0 + 8 * lc);
        }
        asm volatile("cp.async.commit_group;\n" ::);
    };

    #pragma unroll
    for (int p = 0; p < NSTAGE - 1; p++) ld_stage(p, p, true);   // KT=16 > 5

    int s = 0, sld = NSTAGE - 1;
    #pragma unroll 1
    for (int kt = 0; kt < KT; kt++) {
        asm volatile("cp.async.wait_group %0;\n" :: "n"(NSTAGE - 2));
        __syncthreads();

        ld_stage(sld, kt + NSTAGE - 1, kt + NSTAGE - 1 < KT);

        uint4 af[4][2], bf[4];
        #pragma unroll
        for (int mi = 0; mi < 4; mi++) {
            int r0 = wm + mi * 16 + r;
            af[mi][0] = S4[s * 1024 + r0 * 4 + (q ^ ((r0 >> 1) & 3))];
            int r1 = r0 + 8;
            af[mi][1] = S4[s * 1024 + r1 * 4 + (q ^ ((r1 >> 1) & 3))];
        }
        #pragma unroll
        for (int ni = 0; ni < 4; ni++) {
            int rb = wn + ni * 8 + r;
            bf[ni] = S4[s * 1024 + 512 + rb * 4 + (q ^ ((rb >> 1) & 3))];
        }

        #pragma unroll
        for (int mi = 0; mi < 4; mi++)
            #pragma unroll
            for (int ni = 0; ni < 4; ni++)
                mma16(acc[mi][ni], af[mi][0].x, af[mi][1].x, af[mi][0].y, af[mi][1].y,
                      bf[ni].x, bf[ni].y);
        #pragma unroll
        for (int mi = 0; mi < 4; mi++)
            #pragma unroll
            for (int ni = 0; ni < 4; ni++)
                mma16(acc[mi][ni], af[mi][0].z, af[mi][1].z, af[mi][0].w, af[mi][1].w,
                      bf[ni].z, bf[ni].w);

        s = (s + 1 == NSTAGE) ? 0 : s + 1;
        sld = (sld + 1 == NSTAGE) ? 0 : sld + 1;
    }

    // ---- fused LSTM cell epilogue (aliases stage smem after barrier) ----
    const int jbase = blockIdx.x * 32;           // 32 units per block
    const int mbase = blockIdx.y * 128;
    float* Cs = (float*)dsm;                     // [128][33] padded
    float* Hs = Cs + 128 * 33;

    __syncthreads();
    if (!FIRST) {
        #pragma unroll
        for (int k2 = 0; k2 < 4; k2++) {
            int idx = tid + k2 * 256;
            int row = idx >> 3, c4 = (idx & 7) << 2;
            float4 v = *(const float4*)(cmem + (size_t)(mbase + row) * 512 + jbase + c4);
            Cs[row * 33 + c4 + 0] = v.x; Cs[row * 33 + c4 + 1] = v.y;
            Cs[row * 33 + c4 + 2] = v.z; Cs[row * 33 + c4 + 3] = v.w;
        }
    }
    __syncthreads();

    const bool odd = (q & 1);
    #pragma unroll
    for (int ni = 0; ni < 4; ni++) {
        int nloc = wn + ni * 8 + 2 * q;
        float b0v = bias[blockIdx.x * 128 + nloc];
        float b1v = bias[blockIdx.x * 128 + nloc + 1];
        int jloc = nloc >> 2;
        #pragma unroll
        for (int mi = 0; mi < 4; mi++) {
            float v0 = acc[mi][ni][0] + b0v;
            float v1 = acc[mi][ni][1] + b1v;
            float v2 = acc[mi][ni][2] + b0v;
            float v3 = acc[mi][ni][3] + b1v;
            // even lane holds (i,f) both rows; odd lane holds (g,o) both rows.
            float s0 = odd ? v0 : v2;
            float s1 = odd ? v1 : v3;
            float rx0 = __shfl_xor_sync(0xffffffffu, s0, 1);
            float rx1 = __shfl_xor_sync(0xffffffffu, s1, 1);
            float gi = odd ? rx0 : v0;
            float gf = odd ? rx1 : v1;
            float gg = odd ? v2 : rx0;
            float go = odd ? v3 : rx1;
            int mloc = wm + mi * 16 + r + (odd ? 8 : 0);
            float ii = fsig(gi), ff = fsig(gf);
            float gv = ftanh(gg), oo = fsig(go);
            float cn = FIRST ? (ii * gv) : fmaf(ff, Cs[mloc * 33 + jloc], ii * gv);
            Cs[mloc * 33 + jloc] = cn;
            Hs[mloc * 33 + jloc] = oo * ftanh(cn);
        }
    }
    __syncthreads();

    // coalesced stores: c, out[b,t,:], permuted fp16 h for next step
    #pragma unroll
    for (int k2 = 0; k2 < 4; k2++) {
        int idx = tid + k2 * 256;
        int row = idx >> 3, c4 = (idx & 7) << 2;
        int gm = mbase + row;
        float4 cv = make_float4(Cs[row * 33 + c4 + 0], Cs[row * 33 + c4 + 1],
                                Cs[row * 33 + c4 + 2], Cs[row * 33 + c4 + 3]);
        *(float4*)(cmem + (size_t)gm * 512 + jbase + c4) = cv;
        float4 hv = make_float4(Hs[row * 33 + c4 + 0], Hs[row * 33 + c4 + 1],
                                Hs[row * 33 + c4 + 2], Hs[row * 33 + c4 + 3]);
        *(float4*)(outp + ((size_t)gm * T + t) * 512 + jbase + c4) = hv;
        // stored pairs j0, j0+1 take source pairs perm16(j0), perm16(j0+1)
        int j0 = c4 >> 1;
        int s0 = perm16(j0) << 1, s1 = perm16(j0 + 1) << 1;
        __half2 h2a = __floats2half2_rn(Hs[row * 33 + s0], Hs[row * 33 + s0 + 1]);
        __half2 h2b = __floats2half2_rn(Hs[row * 33 + s1], Hs[row * 33 + s1 + 1]);
        uint2 pk;
        pk.x = *(unsigned*)&h2a;
        pk.y = *(unsigned*)&h2b;
        *(uint2*)(hout + (size_t)gm * 512 + jbase + c4) = pk;
    }
}

// ---------------------------------------------------------------------------
// launch
// ---------------------------------------------------------------------------
extern "C" void kernel_launch(void* const* d_in, const int* in_sizes, int n_in,
                              void* d_out, int out_size)
{
    const float* x   = (const float*)d_in[0];
    const float* W1  = (const float*)d_in[1];
    const float* b1  = (const float*)d_in[2];
    const float* W2  = (const float*)d_in[3];
    const float* b2  = (const float*)d_in[4];
    const float* W3  = (const float*)d_in[5];
    const float* b3  = (const float*)d_in[6];
    const float* Wih = (const float*)d_in[7];
    const float* Whh = (const float*)d_in[8];
    const float* bih = (const float*)d_in[9];
    const float* bhh = (const float*)d_in[10];
    const int*   sl  = (const int*)d_in[11];
    float* out = (float*)d_out;

    const int B = in_sizes[0] / 256;          // 8192
    const int T = out_size / (B * 512);       // 16

    __half *W1x_, *WcombI_, *WihI_, *W2p_, *W3p_, *xp_, *h1_, *h2_, *hA_, *hB_;
    float *b1eff_, *biascI_, *c_;
    cudaGetSymbolAddress((void**)&W1x_,    g_W1x);
    cudaGetSymbolAddress((void**)&b1eff_,  g_b1eff);
    cudaGetSymbolAddress((void**)&WcombI_, g_WcombI);
    cudaGetSymbolAddress((void**)&WihI_,   g_WihI);
    cudaGetSymbolAddress((void**)&biascI_, g_biascI);
    cudaGetSymbolAddress((void**)&W2p_,    g_W2p);
    cudaGetSymbolAddress((void**)&W3p_,    g_W3p);
    cudaGetSymbolAddress((void**)&xp_,     g_xp);
    cudaGetSymbolAddress((void**)&h1_,     g_h1);
    cudaGetSymbolAddress((void**)&h2_,     g_h2);
    cudaGetSymbolAddress((void**)&hA_,     g_hA);
    cudaGetSymbolAddress((void**)&hB_,     g_hB);
    cudaGetSymbolAddress((void**)&c_,      g_c);

    cudaFuncSetAttribute(gemm_mlp<1>, cudaFuncAttributeMaxDynamicSharedMemorySize, SMEM_BYTES);
    cudaFuncSetAttribute(gemm_mlp<2>, cudaFuncAttributeMaxDynamicSharedMemorySize, SMEM_BYTES);
    cudaFuncSetAttribute(gemm_lstm<1>, cudaFuncAttributeMaxDynamicSharedMemorySize, SMEM_BYTES);
    cudaFuncSetAttribute(gemm_lstm<0>, cudaFuncAttributeMaxDynamicSharedMemorySize, SMEM_BYTES);

    dim3 blk(256);
    dim3 gMLP(512 / 128, B / 128);    // (4, 64)
    dim3 gGate(16, B / 128);          // (16, 64)

    int prep_threads = B * 256;
    prep_kernel<<<(prep_threads + 255) / 256, 256>>>(x, W1, b1, W2, W3,
                                                     Wih, Whh, bih, bhh, sl, B);

    // MLP
    gemm_mlp<1><<<gMLP, blk, SMEM_BYTES>>>(xp_, 256, W1x_, 256, b1eff_, h1_, 512, 256);
    gemm_mlp<1><<<gMLP, blk, SMEM_BYTES>>>(h1_, 512, W2p_, 512, b2,     h2_, 512, 512);
    gemm_mlp<2><<<gMLP, blk, SMEM_BYTES>>>(h2_, 512, W3p_, 512, b3,     hA_, 512, 512); // x0

    // LSTM: fused gates GEMM + cell, h double-buffered
    __half* hin = hA_;
    __half* hout = hB_;
    for (int t = 0; t < T; ++t) {
        const __half* Wg = (t == 0) ? WihI_ : WcombI_;
        if (t == 0)
            gemm_lstm<1><<<gGate, blk, SMEM_BYTES>>>(hin, Wg, biascI_, c_, out, hout, t, T);
        else
            gemm_lstm<0><<<gGate, blk, SMEM_BYTES>>>(hin, Wg, biascI_, c_, out, hout, t, T);
        __half* tmp = hin; hin = hout; hout = tmp;
    }
}

// round 14
// speedup vs baseline: 1.1731x; 1.1731x over previous
#include <cuda_runtime.h>
#include <cuda_fp16.h>
#include <math.h>

// ---------------------------------------------------------------------------
//   x:[B,256]  W1:[512,273] b1:[512]  W2:[512,512] b2  W3:[512,512] b3
//   Wih:[2048,512] Whh:[2048,512] bih:[2048] bhh:[2048]  sentence_len (int)
//   out:[B,T,512] fp32
//
// compute_103 virtual arch -> no tcgen05. fp16 mma.sync m16n8k16 (fp32 acc),
// pair-permuted fp16 operands (pure cp.async + LDS.128 + HMMA mainloop).
// R6-proven structure: BK=32, 3-stage static-smem pipeline, stride-4 uint4
// rows with 2-bit XOR swizzle. THIS ROUND: compile-time KT + fully unrolled
// mainloop so every stage index / smem offset is an immediate.
// LSTM algebra: inp==h after step 0 -> Wcomb = Wih+Whh halves LSTM FLOPs.
// LSTM cell fused into gates-GEMM epilogue (gate-interleaved N + lane^1).
// ---------------------------------------------------------------------------

#define MAXB 8192

__device__ __align__(256) __half g_W1x[512 * 256];      // perm half W1[:,17:273]
__device__ __align__(256) float  g_b1eff[512];          // b1 + W1[:, 20-len]
__device__ __align__(256) __half g_WcombI[2048 * 512];  // gate-interleaved perm (Wih+Whh)
__device__ __align__(256) __half g_WihI[2048 * 512];    // gate-interleaved perm Wih (t=0)
__device__ __align__(256) float  g_biascI[2048];        // gate-interleaved bih+bhh
__device__ __align__(256) __half g_W2p[512 * 512];
__device__ __align__(256) __half g_W3p[512 * 512];
__device__ __align__(256) __half g_xp[MAXB * 256];      // perm half x
__device__ __align__(256) __half g_h1[MAXB * 512];
__device__ __align__(256) __half g_h2[MAXB * 512];
__device__ __align__(256) __half g_hA[MAXB * 512];      // perm half h ping
__device__ __align__(256) __half g_hB[MAXB * 512];      // perm half h pong
__device__ __align__(256) float  g_c[MAXB * 512];

// ---------------------------------------------------------------------------
// helpers
// ---------------------------------------------------------------------------
// involutive permutation on 4-bit index: swap the two 2-bit fields.
// Applied to PAIR indices within 16-pair (32-half) blocks.
__device__ __host__ __forceinline__ int perm16(int p) {
    return (p & ~15) | ((p & 3) << 2) | ((p >> 2) & 3);
}
// stored half position -> original k
__device__ __forceinline__ int kmap(int pos) {
    return (pos & ~31) | (perm16((pos >> 1) & 15) << 1) | (pos & 1);
}

__device__ __forceinline__ float fsig(float x)  { return 1.f / (1.f + __expf(-x)); }
__device__ __forceinline__ float ftanh(float x) { return 2.f / (1.f + __expf(-2.f * x)) - 1.f; }
__device__ __forceinline__ float sigacc(float x) { return 1.f / (1.f + expf(-x)); }

__device__ __forceinline__ void cpasync16(void* dst, const void* src) {
    unsigned d = (unsigned)__cvta_generic_to_shared(dst);
    asm volatile("cp.async.cg.shared.global [%0], [%1], 16;\n" :: "r"(d), "l"(src));
}

__device__ __forceinline__ void mma16(float* c,
                                      unsigned a0, unsigned a1, unsigned a2, unsigned a3,
                                      unsigned b0, unsigned b1) {
    asm volatile(
        "mma.sync.aligned.m16n8k16.row.col.f32.f16.f16.f32 "
        "{%0,%1,%2,%3}, {%4,%5,%6,%7}, {%8,%9}, {%0,%1,%2,%3};\n"
        : "+f"(c[0]), "+f"(c[1]), "+f"(c[2]), "+f"(c[3])
        : "r"(a0), "r"(a1), "r"(a2), "r"(a3), "r"(b0), "r"(b1));
}

// ---------------------------------------------------------------------------
// prep: permuted fp16 operand copies, fused biases.
// ---------------------------------------------------------------------------
__global__ void prep_kernel(const float* __restrict__ x,
                            const float* __restrict__ W1, const float* __restrict__ b1,
                            const float* __restrict__ W2, const float* __restrict__ W3,
                            const float* __restrict__ Wih, const float* __restrict__ Whh,
                            const float* __restrict__ bih, const float* __restrict__ bhh,
                            const int* __restrict__ slen, int B)
{
    int i = blockIdx.x * blockDim.x + threadIdx.x;

    if (i < 2048 * 512) {                       // LSTM weights: interleave N, permute K
        int np = i >> 9, p = i & 511;
        int gate = np & 3, j = np >> 2;
        int orig = (gate * 512 + j) * 512 + kmap(p);
        float wv = Wih[orig];
        float wh = Whh[orig];
        g_WihI[i]   = __float2half_rn(wv);
        g_WcombI[i] = __float2half_rn(wv + wh);
    }
    if (i < 512 * 512) {                        // W2, W3 (K-permuted)
        int n = i >> 9, p = i & 511;
        int k = kmap(p);
        g_W2p[i] = __float2half_rn(W2[n * 512 + k]);
        g_W3p[i] = __float2half_rn(W3[n * 512 + k]);
    }
    if (i < 512 * 256) {                        // W1 noise columns
        int n = i >> 8, p = i & 255;
        g_W1x[i] = __float2half_rn(W1[n * 273 + 17 + kmap(p)]);
    }
    if (i < B * 256) {                          // x permuted fp16
        int b = i >> 8, p = i & 255;
        g_xp[i] = __float2half_rn(x[b * 256 + kmap(p)]);
    }
    if (i < 2048) {                             // interleaved fused bias
        int gate = i & 3, j = i >> 2;
        g_biascI[i] = bih[gate * 512 + j] + bhh[gate * 512 + j];
    }
    if (i < 512) {
        int hot = 20 - *slen;
        g_b1eff[i] = b1[i] + W1[i * 273 + hot];
    }
}

// ---------------------------------------------------------------------------
// MLP GEMM: C[M,N] = act( A[M,K] * W[N,K]^T + bias[N] ), half operands,
// pair-permuted K. Block 128x128, BK=32 halves, 3-stage cp.async (static
// smem), 8 warps (2x4), warp 64x32, mma m16n8k16. KT = K/32 compile-time,
// mainloop fully unrolled. ACT: 1=relu, 2=sigmoid. Stores permuted half.
// ---------------------------------------------------------------------------
template <int ACT, int KT>
__global__ __launch_bounds__(256, 2)
void gemm_mlp(const __half* __restrict__ A, int lda,
              const __half* __restrict__ Bm, int ldb,
              const float* __restrict__ bias,
              __half* __restrict__ C, int ldc)
{
    __shared__ uint4 As[3][512];                 // 128 rows x 4 chunks(16B)
    __shared__ uint4 Bs[3][512];

    const int tid  = threadIdx.x;
    const int lane = tid & 31;
    const int warp = tid >> 5;
    const int wm = (warp >> 2) * 64;
    const int wn = (warp & 3) * 32;
    const int r = lane >> 2;
    const int q = lane & 3;

    const __half* Ab = A  + (size_t)blockIdx.y * 128 * lda;
    const __half* Bb = Bm + (size_t)blockIdx.x * 128 * ldb;

    const int lr = tid >> 2;
    const int lc = tid & 3;

    float acc[4][4][4];
    #pragma unroll
    for (int i = 0; i < 4; i++)
        #pragma unroll
        for (int j = 0; j < 4; j++)
            #pragma unroll
            for (int k = 0; k < 4; k++) acc[i][j][k] = 0.f;

    auto ld_stage = [&](int s, int kt) {
        const int k0 = kt << 5;
        int row = lr;
        cpasync16(&As[s][row * 4 + (lc ^ ((row >> 1) & 3))], Ab + (size_t)row * lda + k0 + 8 * lc);
        cpasync16(&Bs[s][row * 4 + (lc ^ ((row >> 1) & 3))], Bb + (size_t)row * ldb + k0 + 8 * lc);
        row = lr + 64;
        cpasync16(&As[s][row * 4 + (lc ^ ((row >> 1) & 3))], Ab + (size_t)row * lda + k0 + 8 * lc);
        cpasync16(&Bs[s][row * 4 + (lc ^ ((row >> 1) & 3))], Bb + (size_t)row * ldb + k0 + 8 * lc);
        asm volatile("cp.async.commit_group;\n" ::);
    };

    ld_stage(0, 0);
    ld_stage(1, 1);

    #pragma unroll
    for (int kt = 0; kt < KT; kt++) {
        const int s = kt % 3;                    // compile-time under unroll
        if (kt >= KT - 2) asm volatile("cp.async.wait_group 0;\n" ::);
        else              asm volatile("cp.async.wait_group 1;\n" ::);
        __syncthreads();

        const int ktn = kt + 2;
        if (ktn < KT) ld_stage(ktn % 3, ktn);

        // uint4 per row: x=pair q, y=pair q+4, z=pair q+8, w=pair q+12
        uint4 af[4][2], bf[4];
        #pragma unroll
        for (int mi = 0; mi < 4; mi++) {
            int r0 = wm + mi * 16 + r;
            af[mi][0] = As[s][r0 * 4 + (q ^ ((r0 >> 1) & 3))];
            int r1 = r0 + 8;
            af[mi][1] = As[s][r1 * 4 + (q ^ ((r1 >> 1) & 3))];
        }
        #pragma unroll
        for (int ni = 0; ni < 4; ni++) {
            int rb = wn + ni * 8 + r;
            bf[ni] = Bs[s][rb * 4 + (q ^ ((rb >> 1) & 3))];
        }

        #pragma unroll
        for (int mi = 0; mi < 4; mi++)
            #pragma unroll
            for (int ni = 0; ni < 4; ni++)
                mma16(acc[mi][ni], af[mi][0].x, af[mi][1].x, af[mi][0].y, af[mi][1].y,
                      bf[ni].x, bf[ni].y);
        #pragma unroll
        for (int mi = 0; mi < 4; mi++)
            #pragma unroll
            for (int ni = 0; ni < 4; ni++)
                mma16(acc[mi][ni], af[mi][0].z, af[mi][1].z, af[mi][0].w, af[mi][1].w,
                      bf[ni].z, bf[ni].w);
    }

    #pragma unroll
    for (int mi = 0; mi < 4; mi++) {
        int m0 = blockIdx.y * 128 + wm + mi * 16 + r;
        #pragma unroll
        for (int ni = 0; ni < 4; ni++) {
            int n = blockIdx.x * 128 + wn + ni * 8 + 2 * q;
            float b0v = bias[n], b1v = bias[n + 1];
            float v00 = acc[mi][ni][0] + b0v, v01 = acc[mi][ni][1] + b1v;
            float v10 = acc[mi][ni][2] + b0v, v11 = acc[mi][ni][3] + b1v;
            if (ACT == 1) {
                v00 = fmaxf(v00, 0.f); v01 = fmaxf(v01, 0.f);
                v10 = fmaxf(v10, 0.f); v11 = fmaxf(v11, 0.f);
            } else {
                v00 = sigacc(v00); v01 = sigacc(v01);
                v10 = sigacc(v10); v11 = sigacc(v11);
            }
            // (n, n+1) is one K-pair: store half2 at the permuted pair slot
            int sp = (n & ~31) | (perm16((n >> 1) & 15) << 1);
            *(__half2*)(C + (size_t)m0 * ldc + sp)       = __floats2half2_rn(v00, v01);
            *(__half2*)(C + (size_t)(m0 + 8) * ldc + sp) = __floats2half2_rn(v10, v11);
        }
    }
}

// ---------------------------------------------------------------------------
// Fused gates-GEMM + LSTM cell (same unrolled BK=32 mainloop, KT=16).
// ---------------------------------------------------------------------------
template <int FIRST>
__global__ __launch_bounds__(256, 2)
void gemm_lstm(const __half* __restrict__ A,     // hin [B,512] perm half
               const __half* __restrict__ Bm,    // WgI [2048,512]
               const float* __restrict__ bias,   // biascI [2048]
               float* __restrict__ cmem,         // g_c [B,512]
               float* __restrict__ outp,         // out [B,T,512]
               __half* __restrict__ hout,        // next h [B,512] perm half
               int t, int T)
{
    __shared__ uint4 SM4[3072];                  // 48KB: pipeline, then tiles
    uint4* As = SM4;
    uint4* Bs = SM4 + 1536;

    const int tid  = threadIdx.x;
    const int lane = tid & 31;
    const int warp = tid >> 5;
    const int wm = (warp >> 2) * 64;
    const int wn = (warp & 3) * 32;
    const int r = lane >> 2;
    const int q = lane & 3;

    const __half* Ab = A  + (size_t)blockIdx.y * 128 * 512;
    const __half* Bb = Bm + (size_t)blockIdx.x * 128 * 512;

    const int lr = tid >> 2;
    const int lc = tid & 3;
    constexpr int KT = 16;                       // K = 512 halves / 32

    float acc[4][4][4];
    #pragma unroll
    for (int i = 0; i < 4; i++)
        #pragma unroll
        for (int j = 0; j < 4; j++)
            #pragma unroll
            for (int k = 0; k < 4; k++) acc[i][j][k] = 0.f;

    auto ld_stage = [&](int s, int kt) {
        const int k0 = kt << 5;
        int row = lr;
        cpasync16(&As[s * 512 + row * 4 + (lc ^ ((row >> 1) & 3))], Ab + (size_t)row * 512 + k0 + 8 * lc);
        cpasync16(&Bs[s * 512 + row * 4 + (lc ^ ((row >> 1) & 3))], Bb + (size_t)row * 512 + k0 + 8 * lc);
        row = lr + 64;
        cpasync16(&As[s * 512 + row * 4 + (lc ^ ((row >> 1) & 3))], Ab + (size_t)row * 512 + k0 + 8 * lc);
        cpasync16(&Bs[s * 512 + row * 4 + (lc ^ ((row >> 1) & 3))], Bb + (size_t)row * 512 + k0 + 8 * lc);
        asm volatile("cp.async.commit_group;\n" ::);
    };

    ld_stage(0, 0);
    ld_stage(1, 1);

    #pragma unroll
    for (int kt = 0; kt < KT; kt++) {
        const int s = kt % 3;                    // compile-time under unroll
        if (kt >= KT - 2) asm volatile("cp.async.wait_group 0;\n" ::);
        else              asm volatile("cp.async.wait_group 1;\n" ::);
        __syncthreads();

        const int ktn = kt + 2;
        if (ktn < KT) ld_stage(ktn % 3, ktn);

        uint4 af[4][2], bf[4];
        #pragma unroll
        for (int mi = 0; mi < 4; mi++) {
            int r0 = wm + mi * 16 + r;
            af[mi][0] = As[s * 512 + r0 * 4 + (q ^ ((r0 >> 1) & 3))];
            int r1 = r0 + 8;
            af[mi][1] = As[s * 512 + r1 * 4 + (q ^ ((r1 >> 1) & 3))];
        }
        #pragma unroll
        for (int ni = 0; ni < 4; ni++) {
            int rb = wn + ni * 8 + r;
            bf[ni] = Bs[s * 512 + rb * 4 + (q ^ ((rb >> 1) & 3))];
        }

        #pragma unroll
        for (int mi = 0; mi < 4; mi++)
            #pragma unroll
            for (int ni = 0; ni < 4; ni++)
                mma16(acc[mi][ni], af[mi][0].x, af[mi][1].x, af[mi][0].y, af[mi][1].y,
                      bf[ni].x, bf[ni].y);
        #pragma unroll
        for (int mi = 0; mi < 4; mi++)
            #pragma unroll
            for (int ni = 0; ni < 4; ni++)
                mma16(acc[mi][ni], af[mi][0].z, af[mi][1].z, af[mi][0].w, af[mi][1].w,
                      bf[ni].z, bf[ni].w);
    }

    // ---- fused LSTM cell epilogue ----
    const int jbase = blockIdx.x * 32;           // 32 units per block
    const int mbase = blockIdx.y * 128;
    float* Cs = (float*)SM4;                     // [128][33] padded
    float* Hs = Cs + 128 * 33;

    __syncthreads();
    if (!FIRST) {
        #pragma unroll
        for (int k2 = 0; k2 < 4; k2++) {
            int idx = tid + k2 * 256;
            int row = idx >> 3, c4 = (idx & 7) << 2;
            float4 v = *(const float4*)(cmem + (size_t)(mbase + row) * 512 + jbase + c4);
            Cs[row * 33 + c4 + 0] = v.x; Cs[row * 33 + c4 + 1] = v.y;
            Cs[row * 33 + c4 + 2] = v.z; Cs[row * 33 + c4 + 3] = v.w;
        }
    }
    __syncthreads();

    const bool odd = (q & 1);
    #pragma unroll
    for (int ni = 0; ni < 4; ni++) {
        int nloc = wn + ni * 8 + 2 * q;
        float b0v = bias[blockIdx.x * 128 + nloc];
        float b1v = bias[blockIdx.x * 128 + nloc + 1];
        int jloc = nloc >> 2;
        #pragma unroll
        for (int mi = 0; mi < 4; mi++) {
            float v0 = acc[mi][ni][0] + b0v;
            float v1 = acc[mi][ni][1] + b1v;
            float v2 = acc[mi][ni][2] + b0v;
            float v3 = acc[mi][ni][3] + b1v;
            // even lane holds (i,f) both rows; odd lane holds (g,o) both rows.
            float s0 = odd ? v0 : v2;
            float s1 = odd ? v1 : v3;
            float rx0 = __shfl_xor_sync(0xffffffffu, s0, 1);
            float rx1 = __shfl_xor_sync(0xffffffffu, s1, 1);
            float gi = odd ? rx0 : v0;
            float gf = odd ? rx1 : v1;
            float gg = odd ? v2 : rx0;
            float go = odd ? v3 : rx1;
            int mloc = wm + mi * 16 + r + (odd ? 8 : 0);
            float ii = fsig(gi), ff = fsig(gf);
            float gv = ftanh(gg), oo = fsig(go);
            float cn = FIRST ? (ii * gv) : fmaf(ff, Cs[mloc * 33 + jloc], ii * gv);
            Cs[mloc * 33 + jloc] = cn;
            Hs[mloc * 33 + jloc] = oo * ftanh(cn);
        }
    }
    __syncthreads();

    // coalesced stores: c, out[b,t,:], permuted fp16 h for next step
    #pragma unroll
    for (int k2 = 0; k2 < 4; k2++) {
        int idx = tid + k2 * 256;
        int row = idx >> 3, c4 = (idx & 7) << 2;
        int gm = mbase + row;
        float4 cv = make_float4(Cs[row * 33 + c4 + 0], Cs[row * 33 + c4 + 1],
                                Cs[row * 33 + c4 + 2], Cs[row * 33 + c4 + 3]);
        *(float4*)(cmem + (size_t)gm * 512 + jbase + c4) = cv;
        float4 hv = make_float4(Hs[row * 33 + c4 + 0], Hs[row * 33 + c4 + 1],
                                Hs[row * 33 + c4 + 2], Hs[row * 33 + c4 + 3]);
        *(float4*)(outp + ((size_t)gm * T + t) * 512 + jbase + c4) = hv;
        // stored pairs j0, j0+1 take source pairs perm16(j0), perm16(j0+1)
        int j0 = c4 >> 1;
        int s0 = perm16(j0) << 1, s1 = perm16(j0 + 1) << 1;
        __half2 h2a = __floats2half2_rn(Hs[row * 33 + s0], Hs[row * 33 + s0 + 1]);
        __half2 h2b = __floats2half2_rn(Hs[row * 33 + s1], Hs[row * 33 + s1 + 1]);
        uint2 pk;
        pk.x = *(unsigned*)&h2a;
        pk.y = *(unsigned*)&h2b;
        *(uint2*)(hout + (size_t)gm * 512 + jbase + c4) = pk;
    }
}

// ---------------------------------------------------------------------------
// launch
// ---------------------------------------------------------------------------
extern "C" void kernel_launch(void* const* d_in, const int* in_sizes, int n_in,
                              void* d_out, int out_size)
{
    const float* x   = (const float*)d_in[0];
    const float* W1  = (const float*)d_in[1];
    const float* b1  = (const float*)d_in[2];
    const float* W2  = (const float*)d_in[3];
    const float* b2  = (const float*)d_in[4];
    const float* W3  = (const float*)d_in[5];
    const float* b3  = (const float*)d_in[6];
    const float* Wih = (const float*)d_in[7];
    const float* Whh = (const float*)d_in[8];
    const float* bih = (const float*)d_in[9];
    const float* bhh = (const float*)d_in[10];
    const int*   sl  = (const int*)d_in[11];
    float* out = (float*)d_out;

    const int B = in_sizes[0] / 256;          // 8192
    const int T = out_size / (B * 512);       // 16

    __half *W1x_, *WcombI_, *WihI_, *W2p_, *W3p_, *xp_, *h1_, *h2_, *hA_, *hB_;
    float *b1eff_, *biascI_, *c_;
    cudaGetSymbolAddress((void**)&W1x_,    g_W1x);
    cudaGetSymbolAddress((void**)&b1eff_,  g_b1eff);
    cudaGetSymbolAddress((void**)&WcombI_, g_WcombI);
    cudaGetSymbolAddress((void**)&WihI_,   g_WihI);
    cudaGetSymbolAddress((void**)&biascI_, g_biascI);
    cudaGetSymbolAddress((void**)&W2p_,    g_W2p);
    cudaGetSymbolAddress((void**)&W3p_,    g_W3p);
    cudaGetSymbolAddress((void**)&xp_,     g_xp);
    cudaGetSymbolAddress((void**)&h1_,     g_h1);
    cudaGetSymbolAddress((void**)&h2_,     g_h2);
    cudaGetSymbolAddress((void**)&hA_,     g_hA);
    cudaGetSymbolAddress((void**)&hB_,     g_hB);
    cudaGetSymbolAddress((void**)&c_,      g_c);

    dim3 blk(256);
    dim3 gMLP(512 / 128, B / 128);    // (4, 64)
    dim3 gGate(16, B / 128);          // (16, 64)

    int prep_threads = B * 256;
    prep_kernel<<<(prep_threads + 255) / 256, 256>>>(x, W1, b1, W2, W3,
                                                     Wih, Whh, bih, bhh, sl, B);

    // MLP (KT compile-time: 256/32=8, 512/32=16)
    gemm_mlp<1, 8><<<gMLP, blk>>>(xp_, 256, W1x_, 256, b1eff_, h1_, 512);
    gemm_mlp<1, 16><<<gMLP, blk>>>(h1_, 512, W2p_, 512, b2,     h2_, 512);
    gemm_mlp<2, 16><<<gMLP, blk>>>(h2_, 512, W3p_, 512, b3,     hA_, 512); // x0

    // LSTM: fused gates GEMM + cell, h double-buffered
    __half* hin = hA_;
    __half* hout = hB_;
    for (int t = 0; t < T; ++t) {
        const __half* Wg = (t == 0) ? WihI_ : WcombI_;
        if (t == 0)
            gemm_lstm<1><<<gGate, blk>>>(hin, Wg, biascI_, c_, out, hout, t, T);
        else
            gemm_lstm<0><<<gGate, blk>>>(hin, Wg, biascI_, c_, out, hout, t, T);
        __half* tmp = hin; hin = hout; hout = tmp;
    }
}